// round 3
// baseline (speedup 1.0000x reference)
#include <cuda_runtime.h>
#include <cuda_fp16.h>
#include <cstdint>
#include <cstddef>

#define MDIM 8192
#define NDIM 2048
#define KDIM 2048
// K2 = 4096 (hi/lo fp16 split)

#define BM 128
#define BN 256
#define NS 64              // 4096/64 halfs per stage
#define STAGE_BYTES 49152  // A 16KB + B 32KB
#define SM_BYTES (2 * STAGE_BYTES)

#define TAU 4.0e-3f
#define FLAG_CAP (1 << 20)

__device__ __half g_B2[(size_t)NDIM * 4096];   // [n][k2]: (sign, sign*2^-11) pairs
__device__ int    g_flag_count;
__device__ int2   g_flags[FLAG_CAP];

// ---------------- helpers ----------------
__device__ __forceinline__ uint32_t smem_u32(const void* p) {
    uint32_t a;
    asm("{ .reg .u64 t; cvta.to.shared.u64 t, %1; cvt.u32.u64 %0, t; }" : "=r"(a) : "l"(p));
    return a;
}
__device__ __forceinline__ uint32_t swz(uint32_t off) { return off ^ ((off >> 3) & 0x70); }

__device__ __forceinline__ uint32_t cvt_pair(float v) {
    __half h = __float2half_rn(v);
    __half l = __float2half_rn((v - __half2float(h)) * 2048.0f);
    __half2 p = __halves2half2(h, l);
    return *reinterpret_cast<uint32_t*>(&p);
}

__device__ __forceinline__ void ldsm4(uint32_t* r, uint32_t addr) {
    asm volatile("ldmatrix.sync.aligned.m8n8.x4.shared.b16 {%0,%1,%2,%3}, [%4];"
                 : "=r"(r[0]), "=r"(r[1]), "=r"(r[2]), "=r"(r[3]) : "r"(addr));
}

__device__ __forceinline__ void mma16816(float* c, const uint32_t* a, uint32_t b0, uint32_t b1) {
    asm volatile(
        "mma.sync.aligned.m16n8k16.row.col.f32.f16.f16.f32 "
        "{%0,%1,%2,%3}, {%4,%5,%6,%7}, {%8,%9}, {%0,%1,%2,%3};"
        : "+f"(c[0]), "+f"(c[1]), "+f"(c[2]), "+f"(c[3])
        : "r"(a[0]), "r"(a[1]), "r"(a[2]), "r"(a[3]), "r"(b0), "r"(b1));
}

__device__ __forceinline__ void cp16(uint32_t dst, const void* src) {
    asm volatile("cp.async.cg.shared.global [%0], [%1], 16;" :: "r"(dst), "l"(src));
}
#define CP_COMMIT() asm volatile("cp.async.commit_group;" ::: "memory")
#define CP_WAIT0()  asm volatile("cp.async.wait_group 0;" ::: "memory")

// ---------------- prep: B2[n][2k..2k+1] = (sign(W[k][n]), sign*2^-11) ----------------
__global__ void prep_b_kernel(const float* __restrict__ W) {
    __shared__ float tile[32][33];
    int tx = threadIdx.x, ty = threadIdx.y;
    int k0 = blockIdx.x * 32, n0 = blockIdx.y * 32;
    tile[ty][tx] = W[(size_t)(k0 + ty) * NDIM + (n0 + tx)];
    __syncthreads();
    float w = tile[tx][ty];  // (k = k0+tx, n = n0+ty)
    float s = (w > 0.0f) ? 1.0f : ((w < 0.0f) ? -1.0f : 0.0f);
    __half2 hv = __halves2half2(__float2half_rn(s), __float2half_rn(s * 4.8828125e-4f));
    reinterpret_cast<__half2*>(g_B2)[(size_t)(n0 + ty) * KDIM + (k0 + tx)] = hv;
    if ((blockIdx.x | blockIdx.y | tx | ty) == 0) g_flag_count = 0;
}

// ---------------- GEMM: 128x256 tile, mma.sync m16n8k16, 2-stage pipeline ----------------
__global__ void __launch_bounds__(256, 1) bgemm_kernel(const float* __restrict__ x,
                                                       float* __restrict__ out) {
    extern __shared__ char smem[];
    const uint32_t sb = smem_u32(smem);
    const int tid = threadIdx.x;
    const int wid = tid >> 5;
    const int l   = tid & 31;
    const int wm  = wid & 1;   // 2 warps over M (64 rows each)
    const int wn  = wid >> 1;  // 4 warps over N (64 cols each)
    const int m0 = blockIdx.x * BM;
    const int n0 = blockIdx.y * BN;

    // A producer indices: row = tid&127, half = tid>>7 (16 floats each)
    const int ra   = tid & 127;
    const int ha   = tid >> 7;
    const float4* arow = reinterpret_cast<const float4*>(x + (size_t)(m0 + ra) * KDIM) + ha * 4;
    const uint32_t a_dst_base = swz((uint32_t)ra * 128 + (uint32_t)ha * 64);  // swizzle mask constant per row/j below

    // B producer: row = tid (256 rows), 8x 16B per stage via cp.async
    const uint4* brow = reinterpret_cast<const uint4*>(g_B2) + (size_t)(n0 + tid) * 512;

    // frag smem offsets (unswizzled; swizzle applied per access)
    uint32_t aoff[4], boff[4];
    #pragma unroll
    for (int mf = 0; mf < 4; mf++)
        aoff[mf] = (uint32_t)(wm * 64 + mf * 16 + (l & 15)) * 128 + (uint32_t)((l >> 4) & 1) * 16;
    #pragma unroll
    for (int bg = 0; bg < 4; bg++)
        boff[bg] = (uint32_t)(wn * 64 + bg * 16 + (l & 7) + ((l >> 4) & 1) * 8) * 128
                 + (uint32_t)((l >> 3) & 1) * 16;

    float c[4][8][4];
    #pragma unroll
    for (int i = 0; i < 4; i++)
        #pragma unroll
        for (int j = 0; j < 8; j++)
            #pragma unroll
            for (int e = 0; e < 4; e++) c[i][j][e] = 0.0f;

    float4 av[4];

    // ---- prolog: stage 0 ----
    {
        const uint32_t Bb = sb + 16384;
        #pragma unroll
        for (int j = 0; j < 8; j++)
            cp16(Bb + swz((uint32_t)tid * 128 + j * 16), brow + j);
        CP_COMMIT();
        #pragma unroll
        for (int j = 0; j < 4; j++) av[j] = arow[j];
        char* At = smem;
        #pragma unroll
        for (int j = 0; j < 4; j++) {
            uint4 h;
            h.x = cvt_pair(av[j].x); h.y = cvt_pair(av[j].y);
            h.z = cvt_pair(av[j].z); h.w = cvt_pair(av[j].w);
            *reinterpret_cast<uint4*>(At + swz((uint32_t)ra * 128 + (uint32_t)ha * 64 + j * 16)) = h;
        }
        CP_WAIT0();
        __syncthreads();
    }

    for (int s = 0; s < NS; s++) {
        const int buf = s & 1;
        const int nxt = buf ^ 1;
        const uint32_t Ab = sb + (uint32_t)buf * STAGE_BYTES;
        const uint32_t Bb = Ab + 16384;

        if (s + 1 < NS) {
            // issue next-stage B cp.async + A LDG (latency hidden under mma below)
            const uint32_t Bn = sb + (uint32_t)nxt * STAGE_BYTES + 16384;
            #pragma unroll
            for (int j = 0; j < 8; j++)
                cp16(Bn + swz((uint32_t)tid * 128 + j * 16), brow + (s + 1) * 8 + j);
            CP_COMMIT();
            #pragma unroll
            for (int j = 0; j < 4; j++) av[j] = arow[(s + 1) * 8 + j];
        }

        // ---- compute this stage ----
        #pragma unroll
        for (int ks = 0; ks < 4; ks++) {
            uint32_t af[4][4], bq[4][4];
            #pragma unroll
            for (int mf = 0; mf < 4; mf++)
                ldsm4(af[mf], Ab + swz(aoff[mf] + ks * 32));
            #pragma unroll
            for (int bg = 0; bg < 4; bg++)
                ldsm4(bq[bg], Bb + swz(boff[bg] + ks * 32));
            #pragma unroll
            for (int mf = 0; mf < 4; mf++)
                #pragma unroll
                for (int nf = 0; nf < 8; nf++)
                    mma16816(c[mf][nf], af[mf], bq[nf >> 1][(nf & 1) * 2], bq[nf >> 1][(nf & 1) * 2 + 1]);
        }

        if (s + 1 < NS) {
            char* At = smem + (size_t)nxt * STAGE_BYTES;
            #pragma unroll
            for (int j = 0; j < 4; j++) {
                uint4 h;
                h.x = cvt_pair(av[j].x); h.y = cvt_pair(av[j].y);
                h.z = cvt_pair(av[j].z); h.w = cvt_pair(av[j].w);
                *reinterpret_cast<uint4*>(At + swz((uint32_t)ra * 128 + (uint32_t)ha * 64 + j * 16)) = h;
            }
            CP_WAIT0();
            __syncthreads();
        }
    }

    // ---- epilogue: sign + near-zero flagging ----
    const int g  = l >> 2;
    const int tg = l & 3;
    #pragma unroll
    for (int mf = 0; mf < 4; mf++) {
        const int r0 = m0 + wm * 64 + mf * 16 + g;
        #pragma unroll
        for (int nf = 0; nf < 8; nf++) {
            const int col = n0 + wn * 64 + nf * 8 + 2 * tg;
            float2 lo, hi;
            #pragma unroll
            for (int e = 0; e < 4; e++) {
                float v = c[mf][nf][e];
                if (fabsf(v) < TAU) {
                    int idx = atomicAdd(&g_flag_count, 1);
                    if (idx < FLAG_CAP)
                        g_flags[idx] = make_int2(r0 + (e >> 1) * 8, col + (e & 1));
                }
            }
            lo.x = (c[mf][nf][0] > 0.0f) ? 1.0f : ((c[mf][nf][0] < 0.0f) ? -1.0f : 0.0f);
            lo.y = (c[mf][nf][1] > 0.0f) ? 1.0f : ((c[mf][nf][1] < 0.0f) ? -1.0f : 0.0f);
            hi.x = (c[mf][nf][2] > 0.0f) ? 1.0f : ((c[mf][nf][2] < 0.0f) ? -1.0f : 0.0f);
            hi.y = (c[mf][nf][3] > 0.0f) ? 1.0f : ((c[mf][nf][3] < 0.0f) ? -1.0f : 0.0f);
            *reinterpret_cast<float2*>(out + (size_t)r0 * NDIM + col) = lo;
            *reinterpret_cast<float2*>(out + (size_t)(r0 + 8) * NDIM + col) = hi;
        }
    }
}

// ---------------- fixup: recompute flagged near-zero sums exactly (fp64) ----------------
__global__ void fixup_kernel(const float* __restrict__ x, const float* __restrict__ W,
                             float* __restrict__ out) {
    const int gw  = (blockIdx.x * blockDim.x + threadIdx.x) >> 5;
    const int lid = threadIdx.x & 31;
    const int nw  = (gridDim.x * blockDim.x) >> 5;
    int cnt = g_flag_count;
    if (cnt > FLAG_CAP) cnt = FLAG_CAP;
    for (int i = gw; i < cnt; i += nw) {
        const int m = g_flags[i].x;
        const int n = g_flags[i].y;
        double acc = 0.0;
        for (int k = lid; k < KDIM; k += 32) {
            float w  = W[(size_t)k * NDIM + n];
            float xv = x[(size_t)m * KDIM + k];
            if (w > 0.0f) acc += (double)xv;
            else if (w < 0.0f) acc -= (double)xv;
        }
        #pragma unroll
        for (int o = 16; o; o >>= 1) acc += __shfl_down_sync(0xFFFFFFFFu, acc, o);
        if (lid == 0)
            out[(size_t)m * NDIM + n] = (acc > 0.0) ? 1.0f : ((acc < 0.0) ? -1.0f : 0.0f);
    }
}

// ---------------- launch ----------------
extern "C" void kernel_launch(void* const* d_in, const int* in_sizes, int n_in,
                              void* d_out, int out_size) {
    const float* x = (const float*)d_in[0];
    const float* W = (const float*)d_in[1];
    float* out = (float*)d_out;

    cudaFuncSetAttribute(bgemm_kernel, cudaFuncAttributeMaxDynamicSharedMemorySize, SM_BYTES);

    prep_b_kernel<<<dim3(KDIM / 32, NDIM / 32), dim3(32, 32)>>>(W);
    bgemm_kernel<<<dim3(MDIM / BM, NDIM / BN), 256, SM_BYTES>>>(x, out);
    fixup_kernel<<<128, 256>>>(x, W, out);
}

// round 4
// speedup vs baseline: 1.6823x; 1.6823x over previous
#include <cuda_runtime.h>
#include <cuda_fp16.h>
#include <cstdint>
#include <cstddef>

#define MDIM 8192
#define NDIM 2048
#define KDIM 2048
// K2 = 4096 (hi/lo fp16 split)

#define BM 128
#define BN 256
#define NS 64               // 4096/64 halfs per stage
#define STAGE_BYTES 49152   // A 16KB + B 32KB
#define NSTAGES 4
#define SM_BYTES (NSTAGES * STAGE_BYTES)

#define TAU 4.0e-3f
#define FLAG_CAP (1 << 20)

__device__ __half g_A2[(size_t)MDIM * 4096];   // [m][k2]: (hi, lo*2048) fp16 pairs
__device__ __half g_B2[(size_t)NDIM * 4096];   // [n][k2]: (sign, sign*2^-11) pairs
__device__ int    g_flag_count;
__device__ int2   g_flags[FLAG_CAP];

// ---------------- helpers ----------------
__device__ __forceinline__ uint32_t smem_u32(const void* p) {
    uint32_t a;
    asm("{ .reg .u64 t; cvta.to.shared.u64 t, %1; cvt.u32.u64 %0, t; }" : "=r"(a) : "l"(p));
    return a;
}
__device__ __forceinline__ uint32_t swz(uint32_t off) { return off ^ ((off >> 3) & 0x70); }

__device__ __forceinline__ uint32_t cvt_pair(float v) {
    __half h = __float2half_rn(v);
    __half l = __float2half_rn((v - __half2float(h)) * 2048.0f);
    __half2 p = __halves2half2(h, l);
    return *reinterpret_cast<uint32_t*>(&p);
}

__device__ __forceinline__ void ldsm4(uint32_t* r, uint32_t addr) {
    asm volatile("ldmatrix.sync.aligned.m8n8.x4.shared.b16 {%0,%1,%2,%3}, [%4];"
                 : "=r"(r[0]), "=r"(r[1]), "=r"(r[2]), "=r"(r[3]) : "r"(addr));
}

__device__ __forceinline__ void mma16816(float* c, const uint32_t* a, uint32_t b0, uint32_t b1) {
    asm volatile(
        "mma.sync.aligned.m16n8k16.row.col.f32.f16.f16.f32 "
        "{%0,%1,%2,%3}, {%4,%5,%6,%7}, {%8,%9}, {%0,%1,%2,%3};"
        : "+f"(c[0]), "+f"(c[1]), "+f"(c[2]), "+f"(c[3])
        : "r"(a[0]), "r"(a[1]), "r"(a[2]), "r"(a[3]), "r"(b0), "r"(b1));
}

__device__ __forceinline__ void cp16(uint32_t dst, const void* src) {
    asm volatile("cp.async.cg.shared.global [%0], [%1], 16;" :: "r"(dst), "l"(src));
}
#define CP_COMMIT() asm volatile("cp.async.commit_group;" ::: "memory")
#define CP_WAIT2()  asm volatile("cp.async.wait_group 2;" ::: "memory")
#define CP_WAIT0()  asm volatile("cp.async.wait_group 0;" ::: "memory")

// ---------------- prep A: elementwise hi/lo fp16 split ----------------
__global__ void prep_a_kernel(const float* __restrict__ x) {
    const size_t i = (size_t)blockIdx.x * blockDim.x + threadIdx.x;  // over float4s
    float4 v = reinterpret_cast<const float4*>(x)[i];
    uint4 h;
    h.x = cvt_pair(v.x); h.y = cvt_pair(v.y);
    h.z = cvt_pair(v.z); h.w = cvt_pair(v.w);
    reinterpret_cast<uint4*>(g_A2)[i] = h;
    if (i == 0) g_flag_count = 0;
}

// ---------------- prep B: transpose + sign, fp16 pairs ----------------
__global__ void prep_b_kernel(const float* __restrict__ W) {
    __shared__ float tile[32][33];
    int tx = threadIdx.x, ty = threadIdx.y;
    int k0 = blockIdx.x * 32, n0 = blockIdx.y * 32;
    tile[ty][tx] = W[(size_t)(k0 + ty) * NDIM + (n0 + tx)];
    __syncthreads();
    float w = tile[tx][ty];  // (k = k0+tx, n = n0+ty)
    float s = (w > 0.0f) ? 1.0f : ((w < 0.0f) ? -1.0f : 0.0f);
    __half2 hv = __halves2half2(__float2half_rn(s), __float2half_rn(s * 4.8828125e-4f));
    reinterpret_cast<__half2*>(g_B2)[(size_t)(n0 + ty) * KDIM + (k0 + tx)] = hv;
}

// ---------------- GEMM: 128x256 tile, 512 thr, warp tile 32x64, 4-stage cp.async ----------------
__global__ void __launch_bounds__(512, 1) bgemm_kernel(float* __restrict__ out) {
    extern __shared__ char smem[];
    const uint32_t sb = smem_u32(smem);
    const int tid = threadIdx.x;
    const int wid = tid >> 5;
    const int l   = tid & 31;
    const int wm  = wid & 3;   // 4 warps over M (32 rows each)
    const int wn  = wid >> 2;  // 4 warps over N (64 cols each)
    const int m0 = blockIdx.x * BM;
    const int n0 = blockIdx.y * BN;

    // producer chunk mapping (16B chunks): A 1024 chunks, B 2048 chunks per stage
    const int ar0 = tid >> 2;            // A: 2 chunks -> rows tid>>2 has 4 threads/row? recompute below
    // A: chunk c in [0,1024): row=c>>3, j=c&7 ; thread covers c = tid, tid+512
    // B: chunk c in [0,2048): row=c>>3, j=c&7 ; thread covers c = tid + i*512, i<4
    const uint4* a_src = reinterpret_cast<const uint4*>(g_A2);
    const uint4* b_src = reinterpret_cast<const uint4*>(g_B2);

    // frag smem offsets (unswizzled; swizzle applied per access)
    uint32_t aoff[2], boff[4];
    #pragma unroll
    for (int mf = 0; mf < 2; mf++)
        aoff[mf] = (uint32_t)(wm * 32 + mf * 16 + (l & 15)) * 128 + (uint32_t)((l >> 4) & 1) * 16;
    #pragma unroll
    for (int bg = 0; bg < 4; bg++)
        boff[bg] = (uint32_t)(wn * 64 + bg * 16 + (l & 7) + ((l >> 4) & 1) * 8) * 128
                 + (uint32_t)((l >> 3) & 1) * 16;

    float c[2][8][4];
    #pragma unroll
    for (int i = 0; i < 2; i++)
        #pragma unroll
        for (int j = 0; j < 8; j++)
            #pragma unroll
            for (int e = 0; e < 4; e++) c[i][j][e] = 0.0f;

    // issue one full stage of cp.async
    auto issue_stage = [&](int s, int slot) {
        const uint32_t Ab = sb + (uint32_t)slot * STAGE_BYTES;
        const uint32_t Bb = Ab + 16384;
        #pragma unroll
        for (int i = 0; i < 2; i++) {
            const int cch = tid + i * 512;
            const int row = cch >> 3, j = cch & 7;
            cp16(Ab + swz((uint32_t)row * 128 + j * 16),
                 a_src + (size_t)(m0 + row) * 512 + s * 8 + j);
        }
        #pragma unroll
        for (int i = 0; i < 4; i++) {
            const int cch = tid + i * 512;
            const int row = cch >> 3, j = cch & 7;
            cp16(Bb + swz((uint32_t)row * 128 + j * 16),
                 b_src + (size_t)(n0 + row) * 512 + s * 8 + j);
        }
        CP_COMMIT();
    };

    issue_stage(0, 0);
    issue_stage(1, 1);
    issue_stage(2, 2);

    for (int s = 0; s < NS; s++) {
        CP_WAIT2();
        __syncthreads();
        if (s + 3 < NS) issue_stage(s + 3, (s + 3) & 3);

        const uint32_t Ab = sb + (uint32_t)(s & 3) * STAGE_BYTES;
        const uint32_t Bb = Ab + 16384;
        #pragma unroll
        for (int ks = 0; ks < 4; ks++) {
            uint32_t af[2][4], bq[4][4];
            #pragma unroll
            for (int mf = 0; mf < 2; mf++)
                ldsm4(af[mf], Ab + swz(aoff[mf] + ks * 32));
            #pragma unroll
            for (int bg = 0; bg < 4; bg++)
                ldsm4(bq[bg], Bb + swz(boff[bg] + ks * 32));
            #pragma unroll
            for (int mf = 0; mf < 2; mf++)
                #pragma unroll
                for (int nf = 0; nf < 8; nf++)
                    mma16816(c[mf][nf], af[mf], bq[nf >> 1][(nf & 1) * 2], bq[nf >> 1][(nf & 1) * 2 + 1]);
        }
    }
    CP_WAIT0();

    // ---- epilogue: sign + near-zero flagging ----
    const int g  = l >> 2;
    const int tg = l & 3;
    #pragma unroll
    for (int mf = 0; mf < 2; mf++) {
        const int r0 = m0 + wm * 32 + mf * 16 + g;
        #pragma unroll
        for (int nf = 0; nf < 8; nf++) {
            const int col = n0 + wn * 64 + nf * 8 + 2 * tg;
            #pragma unroll
            for (int e = 0; e < 4; e++) {
                float v = c[mf][nf][e];
                if (fabsf(v) < TAU) {
                    int idx = atomicAdd(&g_flag_count, 1);
                    if (idx < FLAG_CAP)
                        g_flags[idx] = make_int2(r0 + (e >> 1) * 8, col + (e & 1));
                }
            }
            float2 lo, hi;
            lo.x = (c[mf][nf][0] > 0.0f) ? 1.0f : ((c[mf][nf][0] < 0.0f) ? -1.0f : 0.0f);
            lo.y = (c[mf][nf][1] > 0.0f) ? 1.0f : ((c[mf][nf][1] < 0.0f) ? -1.0f : 0.0f);
            hi.x = (c[mf][nf][2] > 0.0f) ? 1.0f : ((c[mf][nf][2] < 0.0f) ? -1.0f : 0.0f);
            hi.y = (c[mf][nf][3] > 0.0f) ? 1.0f : ((c[mf][nf][3] < 0.0f) ? -1.0f : 0.0f);
            *reinterpret_cast<float2*>(out + (size_t)r0 * NDIM + col) = lo;
            *reinterpret_cast<float2*>(out + (size_t)(r0 + 8) * NDIM + col) = hi;
        }
    }
}

// ---------------- fixup: recompute flagged near-zero sums exactly (fp64) ----------------
__global__ void fixup_kernel(const float* __restrict__ x, const float* __restrict__ W,
                             float* __restrict__ out) {
    const int gw  = (blockIdx.x * blockDim.x + threadIdx.x) >> 5;
    const int lid = threadIdx.x & 31;
    const int nw  = (gridDim.x * blockDim.x) >> 5;
    int cnt = g_flag_count;
    if (cnt > FLAG_CAP) cnt = FLAG_CAP;
    for (int i = gw; i < cnt; i += nw) {
        const int m = g_flags[i].x;
        const int n = g_flags[i].y;
        double acc = 0.0;
        for (int k = lid; k < KDIM; k += 32) {
            float w  = W[(size_t)k * NDIM + n];
            float xv = x[(size_t)m * KDIM + k];
            if (w > 0.0f) acc += (double)xv;
            else if (w < 0.0f) acc -= (double)xv;
        }
        #pragma unroll
        for (int o = 16; o; o >>= 1) acc += __shfl_down_sync(0xFFFFFFFFu, acc, o);
        if (lid == 0)
            out[(size_t)m * NDIM + n] = (acc > 0.0) ? 1.0f : ((acc < 0.0) ? -1.0f : 0.0f);
    }
}

// ---------------- launch ----------------
extern "C" void kernel_launch(void* const* d_in, const int* in_sizes, int n_in,
                              void* d_out, int out_size) {
    const float* x = (const float*)d_in[0];
    const float* W = (const float*)d_in[1];
    float* out = (float*)d_out;

    cudaFuncSetAttribute(bgemm_kernel, cudaFuncAttributeMaxDynamicSharedMemorySize, SM_BYTES);

    prep_a_kernel<<<(MDIM * KDIM / 4) / 256, 256>>>(x);
    prep_b_kernel<<<dim3(KDIM / 32, NDIM / 32), dim3(32, 32)>>>(W);
    bgemm_kernel<<<dim3(MDIM / BM, NDIM / BN), 512, SM_BYTES>>>(out);
    fixup_kernel<<<128, 256>>>(x, W, out);
}

// round 6
// speedup vs baseline: 2.8131x; 1.6721x over previous
#include <cuda_runtime.h>
#include <cuda_fp16.h>
#include <cstdint>
#include <cstddef>

#define MDIM 8192
#define NDIM 2048
#define KDIM 2048

#define BM 128
#define BN 256
#define NS 32               // 2048/64 halfs per stage
#define STAGE_BYTES 49152   // A 16KB + B 32KB
#define NSTAGES 4
#define SM_BYTES (NSTAGES * STAGE_BYTES)

#define TAU 0.05f
#define FLAG_CAP (1 << 20)

__device__ __half g_A2[(size_t)MDIM * KDIM];   // [m][k]: fp16(x)
__device__ __half g_B2[(size_t)NDIM * KDIM];   // [n][k]: sign(W) as fp16 (n-major!)
__device__ int    g_flag_count;
__device__ int2   g_flags[FLAG_CAP];

// ---------------- helpers ----------------
__device__ __forceinline__ uint32_t smem_u32(const void* p) {
    uint32_t a;
    asm("{ .reg .u64 t; cvta.to.shared.u64 t, %1; cvt.u32.u64 %0, t; }" : "=r"(a) : "l"(p));
    return a;
}
__device__ __forceinline__ uint32_t swz(uint32_t off) { return off ^ ((off >> 3) & 0x70); }

__device__ __forceinline__ void ldsm4(uint32_t* r, uint32_t addr) {
    asm volatile("ldmatrix.sync.aligned.m8n8.x4.shared.b16 {%0,%1,%2,%3}, [%4];"
                 : "=r"(r[0]), "=r"(r[1]), "=r"(r[2]), "=r"(r[3]) : "r"(addr));
}

__device__ __forceinline__ void mma16816(float* c, const uint32_t* a, uint32_t b0, uint32_t b1) {
    asm volatile(
        "mma.sync.aligned.m16n8k16.row.col.f32.f16.f16.f32 "
        "{%0,%1,%2,%3}, {%4,%5,%6,%7}, {%8,%9}, {%0,%1,%2,%3};"
        : "+f"(c[0]), "+f"(c[1]), "+f"(c[2]), "+f"(c[3])
        : "r"(a[0]), "r"(a[1]), "r"(a[2]), "r"(a[3]), "r"(b0), "r"(b1));
}

__device__ __forceinline__ void cp16(uint32_t dst, const void* src) {
    asm volatile("cp.async.cg.shared.global [%0], [%1], 16;" :: "r"(dst), "l"(src));
}
#define CP_COMMIT() asm volatile("cp.async.commit_group;" ::: "memory")
#define CP_WAIT2()  asm volatile("cp.async.wait_group 2;" ::: "memory")
#define CP_WAIT0()  asm volatile("cp.async.wait_group 0;" ::: "memory")

// ---------------- prep A: fp16(x), elementwise ----------------
__global__ void prep_a_kernel(const float* __restrict__ x) {
    const size_t i = (size_t)blockIdx.x * blockDim.x + threadIdx.x;  // over float4s
    float4 v = reinterpret_cast<const float4*>(x)[i];
    __half2 h0 = __floats2half2_rn(v.x, v.y);
    __half2 h1 = __floats2half2_rn(v.z, v.w);
    uint2 pk;
    pk.x = *reinterpret_cast<uint32_t*>(&h0);
    pk.y = *reinterpret_cast<uint32_t*>(&h1);
    reinterpret_cast<uint2*>(g_A2)[i] = pk;
    if (i == 0) g_flag_count = 0;
}

// ---------------- prep B: transpose + sign ----------------
__global__ void prep_b_kernel(const float* __restrict__ W) {
    __shared__ float tile[32][33];
    int tx = threadIdx.x, ty = threadIdx.y;
    int k0 = blockIdx.x * 32, n0 = blockIdx.y * 32;
    tile[ty][tx] = W[(size_t)(k0 + ty) * NDIM + (n0 + tx)];
    __syncthreads();
    float w = tile[tx][ty];  // (k = k0+tx, n = n0+ty)
    float s = (w > 0.0f) ? 1.0f : ((w < 0.0f) ? -1.0f : 0.0f);
    g_B2[(size_t)(n0 + ty) * KDIM + (k0 + tx)] = __float2half_rn(s);
}

// ---------------- GEMM: 128x256 tile, 512 thr, warp tile 32x64, 4-stage cp.async ----------------
__global__ void __launch_bounds__(512, 1) bgemm_kernel(float* __restrict__ out) {
    extern __shared__ char smem[];
    const uint32_t sb = smem_u32(smem);
    const int tid = threadIdx.x;
    const int wid = tid >> 5;
    const int l   = tid & 31;
    const int wm  = wid & 3;   // 4 warps over M (32 rows each)
    const int wn  = wid >> 2;  // 4 warps over N (64 cols each)
    const int m0 = blockIdx.x * BM;
    const int n0 = blockIdx.y * BN;

    const uint4* a_src = reinterpret_cast<const uint4*>(g_A2);  // row stride 256 uint4
    const uint4* b_src = reinterpret_cast<const uint4*>(g_B2);

    uint32_t aoff[2], boff[4];
    #pragma unroll
    for (int mf = 0; mf < 2; mf++)
        aoff[mf] = (uint32_t)(wm * 32 + mf * 16 + (l & 15)) * 128 + (uint32_t)((l >> 4) & 1) * 16;
    #pragma unroll
    for (int bg = 0; bg < 4; bg++)
        boff[bg] = (uint32_t)(wn * 64 + bg * 16 + (l & 7) + ((l >> 4) & 1) * 8) * 128
                 + (uint32_t)((l >> 3) & 1) * 16;

    float c[2][8][4];
    #pragma unroll
    for (int i = 0; i < 2; i++)
        #pragma unroll
        for (int j = 0; j < 8; j++)
            #pragma unroll
            for (int e = 0; e < 4; e++) c[i][j][e] = 0.0f;

    auto issue_stage = [&](int s, int slot) {
        const uint32_t Ab = sb + (uint32_t)slot * STAGE_BYTES;
        const uint32_t Bb = Ab + 16384;
        #pragma unroll
        for (int i = 0; i < 2; i++) {
            const int cch = tid + i * 512;
            const int row = cch >> 3, j = cch & 7;
            cp16(Ab + swz((uint32_t)row * 128 + j * 16),
                 a_src + (size_t)(m0 + row) * 256 + s * 8 + j);
        }
        #pragma unroll
        for (int i = 0; i < 4; i++) {
            const int cch = tid + i * 512;
            const int row = cch >> 3, j = cch & 7;
            cp16(Bb + swz((uint32_t)row * 128 + j * 16),
                 b_src + (size_t)(n0 + row) * 256 + s * 8 + j);
        }
        CP_COMMIT();
    };

    issue_stage(0, 0);
    issue_stage(1, 1);
    issue_stage(2, 2);

    for (int s = 0; s < NS; s++) {
        CP_WAIT2();
        __syncthreads();
        if (s + 3 < NS) issue_stage(s + 3, (s + 3) & 3);

        const uint32_t Ab = sb + (uint32_t)(s & 3) * STAGE_BYTES;
        const uint32_t Bb = Ab + 16384;
        #pragma unroll
        for (int ks = 0; ks < 4; ks++) {
            uint32_t af[2][4], bq[4][4];
            #pragma unroll
            for (int mf = 0; mf < 2; mf++)
                ldsm4(af[mf], Ab + swz(aoff[mf] + ks * 32));
            #pragma unroll
            for (int bg = 0; bg < 4; bg++)
                ldsm4(bq[bg], Bb + swz(boff[bg] + ks * 32));
            #pragma unroll
            for (int mf = 0; mf < 2; mf++)
                #pragma unroll
                for (int nf = 0; nf < 8; nf++)
                    mma16816(c[mf][nf], af[mf], bq[nf >> 1][(nf & 1) * 2], bq[nf >> 1][(nf & 1) * 2 + 1]);
        }
    }
    CP_WAIT0();

    // ---- epilogue: sign + near-zero flagging ----
    const int g  = l >> 2;
    const int tg = l & 3;
    #pragma unroll
    for (int mf = 0; mf < 2; mf++) {
        const int r0 = m0 + wm * 32 + mf * 16 + g;
        #pragma unroll
        for (int nf = 0; nf < 8; nf++) {
            const int col = n0 + wn * 64 + nf * 8 + 2 * tg;
            #pragma unroll
            for (int e = 0; e < 4; e++) {
                float v = c[mf][nf][e];
                if (fabsf(v) < TAU) {
                    int idx = atomicAdd(&g_flag_count, 1);
                    if (idx < FLAG_CAP)
                        g_flags[idx] = make_int2(r0 + (e >> 1) * 8, col + (e & 1));
                }
            }
            float2 lo, hi;
            lo.x = (c[mf][nf][0] > 0.0f) ? 1.0f : ((c[mf][nf][0] < 0.0f) ? -1.0f : 0.0f);
            lo.y = (c[mf][nf][1] > 0.0f) ? 1.0f : ((c[mf][nf][1] < 0.0f) ? -1.0f : 0.0f);
            hi.x = (c[mf][nf][2] > 0.0f) ? 1.0f : ((c[mf][nf][2] < 0.0f) ? -1.0f : 0.0f);
            hi.y = (c[mf][nf][3] > 0.0f) ? 1.0f : ((c[mf][nf][3] < 0.0f) ? -1.0f : 0.0f);
            *reinterpret_cast<float2*>(out + (size_t)r0 * NDIM + col) = lo;
            *reinterpret_cast<float2*>(out + (size_t)(r0 + 8) * NDIM + col) = hi;
        }
    }
}

// ---------------- fixup: coalesced exact fp64 recompute of flagged outputs ----------------
__global__ void fixup_kernel(const float* __restrict__ x, float* __restrict__ out) {
    const int gw  = (blockIdx.x * blockDim.x + threadIdx.x) >> 5;
    const int lid = threadIdx.x & 31;
    const int nw  = (gridDim.x * blockDim.x) >> 5;
    int cnt = g_flag_count;
    if (cnt > FLAG_CAP) cnt = FLAG_CAP;
    for (int i = gw; i < cnt; i += nw) {
        const int m = g_flags[i].x;
        const int n = g_flags[i].y;
        const float4* xr = reinterpret_cast<const float4*>(x + (size_t)m * KDIM);
        const __half2* sr = reinterpret_cast<const __half2*>(g_B2 + (size_t)n * KDIM);
        double acc = 0.0;
        #pragma unroll 4
        for (int k4 = lid; k4 < KDIM / 4; k4 += 32) {
            float4 xv = xr[k4];
            __half2 s0 = sr[k4 * 2];
            __half2 s1 = sr[k4 * 2 + 1];
            float2 f0 = __half22float2(s0);
            float2 f1 = __half22float2(s1);
            acc += (double)(xv.x * f0.x) + (double)(xv.y * f0.y)
                 + (double)(xv.z * f1.x) + (double)(xv.w * f1.y);
        }
        #pragma unroll
        for (int o = 16; o; o >>= 1) acc += __shfl_down_sync(0xFFFFFFFFu, acc, o);
        if (lid == 0)
            out[(size_t)m * NDIM + n] = (acc > 0.0) ? 1.0f : ((acc < 0.0) ? -1.0f : 0.0f);
    }
}

// ---------------- launch ----------------
extern "C" void kernel_launch(void* const* d_in, const int* in_sizes, int n_in,
                              void* d_out, int out_size) {
    const float* x = (const float*)d_in[0];
    const float* W = (const float*)d_in[1];
    float* out = (float*)d_out;

    cudaFuncSetAttribute(bgemm_kernel, cudaFuncAttributeMaxDynamicSharedMemorySize, SM_BYTES);

    prep_a_kernel<<<(MDIM * KDIM / 4) / 256, 256>>>(x);
    prep_b_kernel<<<dim3(KDIM / 32, NDIM / 32), dim3(32, 32)>>>(W);
    bgemm_kernel<<<dim3(MDIM / BM, NDIM / BN), 512, SM_BYTES>>>(out);
    fixup_kernel<<<1024, 256>>>(x, out);
}